// round 1
// baseline (speedup 1.0000x reference)
#include <cuda_runtime.h>
#include <math.h>

// Problem constants
#define B_    2
#define N_    2048
#define MEM_  2048
#define DIM_  1024
#define H_    16
#define D_    64
#define J_    (MEM_ + N_)   // 4096

// Scratch (device globals: allocation-free per harness rules)
__device__ float g_ctx[B_ * J_ * DIM_];         // 32 MB  concat(mem, x)
__device__ float g_q  [B_ * N_ * DIM_];         // 16 MB  Q = X @ Wq
__device__ float g_kv [B_ * J_ * 2 * DIM_];     // 64 MB  KV = ctx @ Wkv
__device__ float g_o  [B_ * N_ * DIM_];         // 16 MB  attention output (pre-Wo)

// ---------------------------------------------------------------------------
// Pack context = concat(mem, x) along sequence dim
// ---------------------------------------------------------------------------
__global__ void pack_ctx_kernel(const float* __restrict__ x,
                                const float* __restrict__ mem) {
    const size_t total4 = (size_t)B_ * J_ * DIM_ / 4;
    size_t idx = (size_t)blockIdx.x * blockDim.x + threadIdx.x;
    if (idx >= total4) return;
    size_t e = idx * 4;
    int b = (int)(e / ((size_t)J_ * DIM_));
    size_t r = e % ((size_t)J_ * DIM_);
    int j = (int)(r / DIM_);
    int c = (int)(r % DIM_);
    float4 v;
    if (j < MEM_) v = *(const float4*)(mem + ((size_t)b * MEM_ + j) * DIM_ + c);
    else          v = *(const float4*)(x   + ((size_t)b * N_ + (j - MEM_)) * DIM_ + c);
    *(float4*)(g_ctx + e) = v;
}

// ---------------------------------------------------------------------------
// SGEMM: C[M,N] = A[M,K] @ B[K,N] (+ bias). All dims multiples of tile sizes.
// BM=128, BN=128, BK=16, 256 threads, 8x8 per-thread micro-tile.
// ---------------------------------------------------------------------------
__global__ void __launch_bounds__(256)
sgemm_kernel(const float* __restrict__ A, const float* __restrict__ Bm,
             float* __restrict__ C, const float* __restrict__ bias,
             int M, int Nn, int K) {
    const int BM = 128, BN = 128, BK = 16;
    __shared__ float As[BK][BM];
    __shared__ float Bs[BK][BN];

    const int tid = threadIdx.x;
    const int tr = tid / 16;          // 0..15 (row group)
    const int tc = tid % 16;          // 0..15 (col group)
    const int mBase = blockIdx.y * BM;
    const int nBase = blockIdx.x * BN;

    // A load mapping: 128 rows x 4 float4/row = 512 float4, 2 per thread
    const int aRow0 = tid / 4;              // 0..63
    const int aCol4 = (tid % 4) * 4;        // 0,4,8,12
    // B load mapping: 16 rows x 32 float4/row = 512 float4, 2 per thread
    const int bRow0 = tid / 32;             // 0..7
    const int bCol4 = (tid % 32) * 4;       // 0..124

    float acc[8][8] = {};

    for (int k0 = 0; k0 < K; k0 += BK) {
        #pragma unroll
        for (int i = 0; i < 2; i++) {
            int ar = aRow0 + i * 64;
            float4 a4 = *(const float4*)(A + (size_t)(mBase + ar) * K + k0 + aCol4);
            As[aCol4 + 0][ar] = a4.x;
            As[aCol4 + 1][ar] = a4.y;
            As[aCol4 + 2][ar] = a4.z;
            As[aCol4 + 3][ar] = a4.w;
        }
        #pragma unroll
        for (int i = 0; i < 2; i++) {
            int br = bRow0 + i * 8;
            *(float4*)(&Bs[br][bCol4]) =
                *(const float4*)(Bm + (size_t)(k0 + br) * Nn + nBase + bCol4);
        }
        __syncthreads();

        #pragma unroll
        for (int k = 0; k < BK; k++) {
            float4 a0 = *(float4*)(&As[k][tr * 8]);
            float4 a1 = *(float4*)(&As[k][tr * 8 + 4]);
            float4 b0 = *(float4*)(&Bs[k][tc * 8]);
            float4 b1 = *(float4*)(&Bs[k][tc * 8 + 4]);
            float a[8] = {a0.x, a0.y, a0.z, a0.w, a1.x, a1.y, a1.z, a1.w};
            float b[8] = {b0.x, b0.y, b0.z, b0.w, b1.x, b1.y, b1.z, b1.w};
            #pragma unroll
            for (int i = 0; i < 8; i++)
                #pragma unroll
                for (int j = 0; j < 8; j++)
                    acc[i][j] += a[i] * b[j];
        }
        __syncthreads();
    }

    #pragma unroll
    for (int i = 0; i < 8; i++) {
        int m = mBase + tr * 8 + i;
        #pragma unroll
        for (int j = 0; j < 8; j += 4) {
            int n = nBase + tc * 8 + j;
            float4 v;
            v.x = acc[i][j + 0];
            v.y = acc[i][j + 1];
            v.z = acc[i][j + 2];
            v.w = acc[i][j + 3];
            if (bias) {
                v.x += bias[n + 0]; v.y += bias[n + 1];
                v.z += bias[n + 2]; v.w += bias[n + 3];
            }
            *(float4*)(C + (size_t)m * Nn + n) = v;
        }
    }
}

// ---------------------------------------------------------------------------
// Flash attention (fp32), causal with memory offset + post-softmax expire mask.
// One block per (b,h, 64-query tile). Online softmax; em folded into numerator.
// ---------------------------------------------------------------------------
#define BQ 64
#define BJ 64
#define AST 68   // smem row stride (floats), 16B-aligned rows

__global__ void __launch_bounds__(256)
attn_kernel(const float* __restrict__ em) {
    extern __shared__ float sm[];
    float* Qs  = sm;                    // [64][68]
    float* Ks  = Qs + BQ * AST;         // [64][68]
    float* Vs  = Ks + BJ * AST;         // [64][68]
    float* Ps  = Vs + BJ * AST;         // [64][68] (S then P)
    float* m_s = Ps + BQ * AST;         // [64]
    float* l_s = m_s + BQ;              // [64]
    float* a_s = l_s + BQ;              // [64] per-row rescale
    float* red = a_s + BQ;              // [256]

    const int tid = threadIdx.x;
    const int bh  = blockIdx.y;
    const int b   = bh / H_;
    const int h   = bh % H_;
    const int q0  = blockIdx.x * BQ;

    const int ty = tid / 16;            // 0..15
    const int tx = tid % 16;            // 0..15

    // Load Q tile with softmax scale folded in (d^-0.5 = 0.125)
    #pragma unroll
    for (int i = 0; i < 4; i++) {
        int idx = tid + i * 256;
        int r = idx / 16;
        int c4 = (idx % 16) * 4;
        float4 v = *(const float4*)(g_q + ((size_t)(b * N_ + q0 + r)) * DIM_ + h * D_ + c4);
        float* dst = Qs + r * AST + c4;
        dst[0] = v.x * 0.125f; dst[1] = v.y * 0.125f;
        dst[2] = v.z * 0.125f; dst[3] = v.w * 0.125f;
    }
    if (tid < BQ) { m_s[tid] = -1e30f; l_s[tid] = 0.0f; }

    float oacc[4][4] = {};

    const int njEnd = q0 + MEM_ + BJ;   // exclusive bound; last tile j0 = q0+MEM_
    for (int j0 = 0; j0 < njEnd; j0 += BJ) {
        __syncthreads();   // protect Ks/Vs/Ps from previous iteration's readers

        // Load K and V tiles
        #pragma unroll
        for (int i = 0; i < 4; i++) {
            int idx = tid + i * 256;
            int r = idx / 16;
            int c4 = (idx % 16) * 4;
            const float* kvb = g_kv + ((size_t)(b * J_ + j0 + r)) * (2 * DIM_);
            *(float4*)(Ks + r * AST + c4) = *(const float4*)(kvb + h * D_ + c4);
            *(float4*)(Vs + r * AST + c4) = *(const float4*)(kvb + DIM_ + h * D_ + c4);
        }
        __syncthreads();

        // S = Qs @ Ks^T  (each thread 4x4)
        float sacc[4][4] = {};
        for (int k = 0; k < D_; k += 4) {
            float4 a4[4], b4[4];
            #pragma unroll
            for (int i = 0; i < 4; i++) a4[i] = *(float4*)(Qs + (ty * 4 + i) * AST + k);
            #pragma unroll
            for (int j = 0; j < 4; j++) b4[j] = *(float4*)(Ks + (tx * 4 + j) * AST + k);
            #pragma unroll
            for (int i = 0; i < 4; i++)
                #pragma unroll
                for (int j = 0; j < 4; j++)
                    sacc[i][j] += a4[i].x * b4[j].x + a4[i].y * b4[j].y +
                                  a4[i].z * b4[j].z + a4[i].w * b4[j].w;
        }

        // Mask (only boundary tile is partial) and stage S in smem
        const bool partial = (j0 + BJ - 1 > q0 + MEM_);
        #pragma unroll
        for (int i = 0; i < 4; i++) {
            int qi = ty * 4 + i;
            #pragma unroll
            for (int j = 0; j < 4; j++) {
                int jj = tx * 4 + j;
                float s = sacc[i][j];
                if (partial && (j0 + jj > q0 + qi + MEM_)) s = -1e30f;
                Ps[qi * AST + jj] = s;
            }
        }
        __syncthreads();

        // Online softmax update: 4 threads per row
        {
            int r = tid >> 2, p = tid & 3;
            float mprev = m_s[r];
            float tmax = mprev;
            #pragma unroll 8
            for (int c = 0; c < BJ; c++) tmax = fmaxf(tmax, Ps[r * AST + c]);
            float lpart = 0.0f;
            const float* emrow = em + (size_t)b * J_ + j0;
            #pragma unroll
            for (int c = p * 16; c < p * 16 + 16; c++) {
                float e = __expf(Ps[r * AST + c] - tmax);
                lpart += e;
                Ps[r * AST + c] = e * __ldg(emrow + c);  // expire gate: numerator only
            }
            red[tid] = lpart;
            __syncthreads();
            if (p == 0) {
                float alpha = __expf(mprev - tmax);
                l_s[r] = l_s[r] * alpha + red[r * 4] + red[r * 4 + 1]
                                        + red[r * 4 + 2] + red[r * 4 + 3];
                m_s[r] = tmax;
                a_s[r] = alpha;
            }
            __syncthreads();
        }

        // Rescale running O and accumulate P @ V
        #pragma unroll
        for (int i = 0; i < 4; i++) {
            float al = a_s[ty * 4 + i];
            #pragma unroll
            for (int j = 0; j < 4; j++) oacc[i][j] *= al;
        }
        for (int jj = 0; jj < BJ; jj += 4) {
            float4 p4[4], v4[4];
            #pragma unroll
            for (int i = 0; i < 4; i++) p4[i] = *(float4*)(Ps + (ty * 4 + i) * AST + jj);
            #pragma unroll
            for (int l = 0; l < 4; l++) v4[l] = *(float4*)(Vs + (jj + l) * AST + tx * 4);
            #pragma unroll
            for (int i = 0; i < 4; i++) {
                oacc[i][0] += p4[i].x * v4[0].x + p4[i].y * v4[1].x + p4[i].z * v4[2].x + p4[i].w * v4[3].x;
                oacc[i][1] += p4[i].x * v4[0].y + p4[i].y * v4[1].y + p4[i].z * v4[2].y + p4[i].w * v4[3].y;
                oacc[i][2] += p4[i].x * v4[0].z + p4[i].y * v4[1].z + p4[i].z * v4[2].z + p4[i].w * v4[3].z;
                oacc[i][3] += p4[i].x * v4[0].w + p4[i].y * v4[1].w + p4[i].z * v4[2].w + p4[i].w * v4[3].w;
            }
        }
    }

    // Finalize: divide by softmax denominator, write to g_o
    #pragma unroll
    for (int i = 0; i < 4; i++) {
        int qi = ty * 4 + i;
        float inv = 1.0f / l_s[qi];
        float4 v;
        v.x = oacc[i][0] * inv; v.y = oacc[i][1] * inv;
        v.z = oacc[i][2] * inv; v.w = oacc[i][3] * inv;
        *(float4*)(g_o + ((size_t)(b * N_ + q0 + qi)) * DIM_ + h * D_ + tx * 4) = v;
    }
}

// ---------------------------------------------------------------------------
// Launch
// ---------------------------------------------------------------------------
extern "C" void kernel_launch(void* const* d_in, const int* in_sizes, int n_in,
                              void* d_out, int out_size) {
    const float* x   = (const float*)d_in[0];
    const float* mem = (const float*)d_in[1];
    const float* em  = (const float*)d_in[2];
    const float* Wq  = (const float*)d_in[3];
    const float* Wkv = (const float*)d_in[4];
    const float* Wo  = (const float*)d_in[5];
    const float* bo  = (const float*)d_in[6];
    float* out = (float*)d_out;

    float *ctxp, *qp, *kvp, *op;
    cudaGetSymbolAddress((void**)&ctxp, g_ctx);
    cudaGetSymbolAddress((void**)&qp,   g_q);
    cudaGetSymbolAddress((void**)&kvp,  g_kv);
    cudaGetSymbolAddress((void**)&op,   g_o);

    // 1) pack context
    {
        size_t total4 = (size_t)B_ * J_ * DIM_ / 4;
        int thr = 256;
        int blk = (int)((total4 + thr - 1) / thr);
        pack_ctx_kernel<<<blk, thr>>>(x, mem);
    }

    // 2) Q = X @ Wq          [4096,1024] = [4096,1024]@[1024,1024]
    {
        dim3 grid(DIM_ / 128, (B_ * N_) / 128);
        sgemm_kernel<<<grid, 256>>>(x, Wq, qp, nullptr, B_ * N_, DIM_, DIM_);
    }

    // 3) KV = ctx @ Wkv      [8192,2048] = [8192,1024]@[1024,2048]
    {
        dim3 grid((2 * DIM_) / 128, (B_ * J_) / 128);
        sgemm_kernel<<<grid, 256>>>(ctxp, Wkv, kvp, nullptr, B_ * J_, 2 * DIM_, DIM_);
    }

    // 4) flash attention -> g_o
    {
        int smemBytes = (4 * BQ * AST + 3 * BQ + 256) * (int)sizeof(float); // ~71.4 KB
        cudaFuncSetAttribute(attn_kernel, cudaFuncAttributeMaxDynamicSharedMemorySize,
                             smemBytes);
        dim3 grid(N_ / BQ, B_ * H_);
        attn_kernel<<<grid, 256, smemBytes>>>(em);
    }

    // 5) out = g_o @ Wo + bo
    {
        dim3 grid(DIM_ / 128, (B_ * N_) / 128);
        sgemm_kernel<<<grid, 256>>>(op, Wo, out, bo, B_ * N_, DIM_, DIM_);
    }
}

// round 2
// speedup vs baseline: 3.2945x; 3.2945x over previous
#include <cuda_runtime.h>
#include <math.h>
#include <stdint.h>

// Problem constants
#define B_    2
#define N_    2048
#define MEM_  2048
#define DIM_  1024
#define H_    16
#define D_    64
#define J_    (MEM_ + N_)   // 4096

// Scratch (device globals: allocation-free per harness rules)
__device__ float g_ctx[B_ * J_ * DIM_];         // 32 MB  concat(mem, x)
__device__ float g_q  [B_ * N_ * DIM_];         // 16 MB  Q = X @ Wq
__device__ float g_kv [B_ * J_ * 2 * DIM_];     // 64 MB  KV = ctx @ Wkv
__device__ float g_o  [B_ * N_ * DIM_];         // 16 MB  attention output (pre-Wo)

// ---------------------------------------------------------------------------
// Helpers
// ---------------------------------------------------------------------------
__device__ __forceinline__ float cvt_tf32(float x) {
    uint32_t u;
    asm("cvt.rna.tf32.f32 %0, %1;" : "=r"(u) : "f"(x));
    return __uint_as_float(u);
}

__device__ __forceinline__ void mma_tf32(float c[4],
                                         uint32_t a0, uint32_t a1, uint32_t a2, uint32_t a3,
                                         uint32_t b0, uint32_t b1) {
    asm volatile(
        "mma.sync.aligned.m16n8k8.row.col.f32.tf32.tf32.f32 "
        "{%0,%1,%2,%3}, {%4,%5,%6,%7}, {%8,%9}, {%0,%1,%2,%3};"
        : "+f"(c[0]), "+f"(c[1]), "+f"(c[2]), "+f"(c[3])
        : "r"(a0), "r"(a1), "r"(a2), "r"(a3), "r"(b0), "r"(b1));
}

// ---------------------------------------------------------------------------
// Pack context = concat(mem, x) along sequence dim
// ---------------------------------------------------------------------------
__global__ void pack_ctx_kernel(const float* __restrict__ x,
                                const float* __restrict__ mem) {
    const size_t total4 = (size_t)B_ * J_ * DIM_ / 4;
    size_t idx = (size_t)blockIdx.x * blockDim.x + threadIdx.x;
    if (idx >= total4) return;
    size_t e = idx * 4;
    int b = (int)(e / ((size_t)J_ * DIM_));
    size_t r = e % ((size_t)J_ * DIM_);
    int j = (int)(r / DIM_);
    int c = (int)(r % DIM_);
    float4 v;
    if (j < MEM_) v = *(const float4*)(mem + ((size_t)b * MEM_ + j) * DIM_ + c);
    else          v = *(const float4*)(x   + ((size_t)b * N_ + (j - MEM_)) * DIM_ + c);
    *(float4*)(g_ctx + e) = v;
}

// ---------------------------------------------------------------------------
// TF32 tensor-core GEMM: C[M,N] = A[M,K] @ B[K,N] (+bias)
// BM=128, BN=128, BK=32, 256 threads (8 warps, 2x4 warp grid, 64x32 warp tile)
// ---------------------------------------------------------------------------
#define G_AST 36    // As stride (words): bank = R*4 + c  -> conflict-free frags
#define G_BST 136   // Bs stride (words): bank = k*8 + n  -> conflict-free frags

__global__ void __launch_bounds__(256)
gemm_tf32(const float* __restrict__ A, const float* __restrict__ Bm,
          float* __restrict__ C, const float* __restrict__ bias,
          int M, int Nn, int K) {
    __shared__ float As[128 * G_AST];
    __shared__ float Bs[32 * G_BST];

    const int tid = threadIdx.x;
    const int w = tid >> 5, lane = tid & 31;
    const int wm = w >> 2, wn = w & 3;     // 2 x 4 warp grid
    const int lr = lane >> 2, lc = lane & 3;
    const int mBase = blockIdx.y * 128;
    const int nBase = blockIdx.x * 128;

    float acc[4][4][4] = {};

    for (int k0 = 0; k0 < K; k0 += 32) {
        // Load A tile 128x32 (cvt to tf32)
        #pragma unroll
        for (int i = 0; i < 4; i++) {
            int idx = tid + i * 256;
            int r = idx >> 3, c4 = (idx & 7) * 4;
            float4 v = *(const float4*)(A + (size_t)(mBase + r) * K + k0 + c4);
            float4 t;
            t.x = cvt_tf32(v.x); t.y = cvt_tf32(v.y);
            t.z = cvt_tf32(v.z); t.w = cvt_tf32(v.w);
            *(float4*)(As + r * G_AST + c4) = t;
        }
        // Load B tile 32x128 (cvt to tf32)
        #pragma unroll
        for (int i = 0; i < 4; i++) {
            int idx = tid + i * 256;
            int r = idx >> 5, c4 = (idx & 31) * 4;
            float4 v = *(const float4*)(Bm + (size_t)(k0 + r) * Nn + nBase + c4);
            float4 t;
            t.x = cvt_tf32(v.x); t.y = cvt_tf32(v.y);
            t.z = cvt_tf32(v.z); t.w = cvt_tf32(v.w);
            *(float4*)(Bs + r * G_BST + c4) = t;
        }
        __syncthreads();

        #pragma unroll
        for (int ks = 0; ks < 32; ks += 8) {
            uint32_t af[4][4], bf[4][2];
            #pragma unroll
            for (int i = 0; i < 4; i++) {
                int R = wm * 64 + i * 16 + lr;
                af[i][0] = __float_as_uint(As[R * G_AST + ks + lc]);
                af[i][1] = __float_as_uint(As[(R + 8) * G_AST + ks + lc]);
                af[i][2] = __float_as_uint(As[R * G_AST + ks + 4 + lc]);
                af[i][3] = __float_as_uint(As[(R + 8) * G_AST + ks + 4 + lc]);
            }
            #pragma unroll
            for (int j = 0; j < 4; j++) {
                int Cn = wn * 32 + j * 8 + lr;
                bf[j][0] = __float_as_uint(Bs[(ks + lc) * G_BST + Cn]);
                bf[j][1] = __float_as_uint(Bs[(ks + lc + 4) * G_BST + Cn]);
            }
            #pragma unroll
            for (int i = 0; i < 4; i++)
                #pragma unroll
                for (int j = 0; j < 4; j++)
                    mma_tf32(acc[i][j], af[i][0], af[i][1], af[i][2], af[i][3],
                             bf[j][0], bf[j][1]);
        }
        __syncthreads();
    }

    // Epilogue
    #pragma unroll
    for (int i = 0; i < 4; i++) {
        int r0 = mBase + wm * 64 + i * 16 + lr;
        #pragma unroll
        for (int j = 0; j < 4; j++) {
            int n0 = nBase + wn * 32 + j * 8 + 2 * lc;
            float b0v = bias ? bias[n0] : 0.0f;
            float b1v = bias ? bias[n0 + 1] : 0.0f;
            float2 v0 = {acc[i][j][0] + b0v, acc[i][j][1] + b1v};
            float2 v1 = {acc[i][j][2] + b0v, acc[i][j][3] + b1v};
            *(float2*)(C + (size_t)r0 * Nn + n0) = v0;
            *(float2*)(C + (size_t)(r0 + 8) * Nn + n0) = v1;
        }
    }
}

// ---------------------------------------------------------------------------
// Flash attention w/ tensor cores (tf32 mma), fp32 softmax.
// BQ=BJ=64, 256 threads (8 warps, 4x2 warp grid).
// S = Q@K^T via mma -> Ps (fp32) -> online softmax (expire gate in numerator)
// -> P (tf32) @ V via mma into persistent register accumulators.
// ---------------------------------------------------------------------------
#define BQ 64
#define BJ 64
#define QST 68   // Qs/Ks/Ps stride: bank = r*4 + c (conflict-free frag loads)
#define VST 72   // Vs stride: bank = k*8 + n (conflict-free B-frag loads)

__global__ void __launch_bounds__(256)
attn_tc_kernel(const float* __restrict__ em) {
    extern __shared__ float smf[];
    float* Qs  = smf;                   // [64][68]
    float* Ks  = Qs + BQ * QST;         // [64][68]
    float* Vs  = Ks + BJ * QST;         // [64][72]
    float* Ps  = Vs + BJ * VST;         // [64][68]
    float* m_s = Ps + BQ * QST;         // [64]
    float* l_s = m_s + BQ;              // [64]
    float* a_s = l_s + BQ;              // [64]
    float* red = a_s + BQ;              // [256]

    const int tid = threadIdx.x;
    const int w = tid >> 5, lane = tid & 31;
    const int lr = lane >> 2, lc = lane & 3;
    const int swm = w >> 1, swn = w & 1;   // 4 x 2 warp grid
    const int bh = blockIdx.y;
    const int b = bh / H_, h = bh % H_;
    const int q0 = blockIdx.x * BQ;
    const int R = swm * 16 + lr;           // this thread's base q-row in tile

    // Load Q tile (scale folded, tf32)
    #pragma unroll
    for (int i = 0; i < 4; i++) {
        int idx = tid + i * 256;
        int r = idx >> 4, c4 = (idx & 15) * 4;
        float4 v = *(const float4*)(g_q + ((size_t)(b * N_ + q0 + r)) * DIM_ + h * D_ + c4);
        float4 t;
        t.x = cvt_tf32(v.x * 0.125f); t.y = cvt_tf32(v.y * 0.125f);
        t.z = cvt_tf32(v.z * 0.125f); t.w = cvt_tf32(v.w * 0.125f);
        *(float4*)(Qs + r * QST + c4) = t;
    }
    if (tid < BQ) { m_s[tid] = -1e30f; l_s[tid] = 0.0f; }

    float oacc[4][4] = {};   // [n-tile][reg] persistent O accumulator

    const int njEnd = q0 + MEM_ + BJ;
    for (int j0 = 0; j0 < njEnd; j0 += BJ) {
        __syncthreads();   // protect Ks/Vs/Ps from previous iteration readers

        // Load K, V tiles (tf32)
        #pragma unroll
        for (int i = 0; i < 4; i++) {
            int idx = tid + i * 256;
            int r = idx >> 4, c4 = (idx & 15) * 4;
            const float* kvb = g_kv + ((size_t)(b * J_ + j0 + r)) * (2 * DIM_);
            float4 kv4 = *(const float4*)(kvb + h * D_ + c4);
            float4 vv4 = *(const float4*)(kvb + DIM_ + h * D_ + c4);
            float4 kt, vt;
            kt.x = cvt_tf32(kv4.x); kt.y = cvt_tf32(kv4.y);
            kt.z = cvt_tf32(kv4.z); kt.w = cvt_tf32(kv4.w);
            vt.x = cvt_tf32(vv4.x); vt.y = cvt_tf32(vv4.y);
            vt.z = cvt_tf32(vv4.z); vt.w = cvt_tf32(vv4.w);
            *(float4*)(Ks + r * QST + c4) = kt;
            *(float4*)(Vs + r * VST + c4) = vt;
        }
        __syncthreads();

        // ---- S = Q @ K^T via mma (warp tile 16 x 32) ----
        float sc[4][4] = {};
        #pragma unroll
        for (int ks = 0; ks < D_; ks += 8) {
            uint32_t a0 = __float_as_uint(Qs[R * QST + ks + lc]);
            uint32_t a1 = __float_as_uint(Qs[(R + 8) * QST + ks + lc]);
            uint32_t a2 = __float_as_uint(Qs[R * QST + ks + 4 + lc]);
            uint32_t a3 = __float_as_uint(Qs[(R + 8) * QST + ks + 4 + lc]);
            #pragma unroll
            for (int j = 0; j < 4; j++) {
                int n = swn * 32 + j * 8 + lr;
                uint32_t b0 = __float_as_uint(Ks[n * QST + ks + lc]);
                uint32_t b1 = __float_as_uint(Ks[n * QST + ks + 4 + lc]);
                mma_tf32(sc[j], a0, a1, a2, a3, b0, b1);
            }
        }

        // Mask (only boundary tile partial) + stage S in Ps (fp32)
        const bool partial = (j0 + BJ - 1 > q0 + MEM_);
        #pragma unroll
        for (int j = 0; j < 4; j++) {
            int col = swn * 32 + j * 8 + 2 * lc;
            float s0 = sc[j][0], s1 = sc[j][1], s2 = sc[j][2], s3 = sc[j][3];
            if (partial) {
                int lim0 = q0 + R + MEM_;       // row R limit
                int lim1 = q0 + R + 8 + MEM_;   // row R+8 limit
                if (j0 + col     > lim0) s0 = -1e30f;
                if (j0 + col + 1 > lim0) s1 = -1e30f;
                if (j0 + col     > lim1) s2 = -1e30f;
                if (j0 + col + 1 > lim1) s3 = -1e30f;
            }
            Ps[R * QST + col] = s0;       Ps[R * QST + col + 1] = s1;
            Ps[(R + 8) * QST + col] = s2; Ps[(R + 8) * QST + col + 1] = s3;
        }
        __syncthreads();

        // ---- Online softmax (4 threads per row), expire gate in numerator ----
        {
            int r = tid >> 2, p = tid & 3;
            float mprev = m_s[r];
            float tmax = mprev;
            #pragma unroll 8
            for (int c = 0; c < BJ; c++) tmax = fmaxf(tmax, Ps[r * QST + c]);
            float lpart = 0.0f;
            const float* emrow = em + (size_t)b * J_ + j0;
            #pragma unroll
            for (int c = p * 16; c < p * 16 + 16; c++) {
                float e = __expf(Ps[r * QST + c] - tmax);
                lpart += e;
                Ps[r * QST + c] = cvt_tf32(e * __ldg(emrow + c));  // P in tf32
            }
            red[tid] = lpart;
            __syncthreads();
            if (p == 0) {
                float alpha = __expf(mprev - tmax);
                l_s[r] = l_s[r] * alpha + red[r * 4] + red[r * 4 + 1]
                                        + red[r * 4 + 2] + red[r * 4 + 3];
                m_s[r] = tmax;
                a_s[r] = alpha;
            }
            __syncthreads();
        }

        // ---- Rescale O, accumulate P @ V via mma ----
        {
            float al0 = a_s[R], al1 = a_s[R + 8];
            #pragma unroll
            for (int j = 0; j < 4; j++) {
                oacc[j][0] *= al0; oacc[j][1] *= al0;
                oacc[j][2] *= al1; oacc[j][3] *= al1;
            }
        }
        #pragma unroll
        for (int ks = 0; ks < BJ; ks += 8) {
            uint32_t a0 = __float_as_uint(Ps[R * QST + ks + lc]);
            uint32_t a1 = __float_as_uint(Ps[(R + 8) * QST + ks + lc]);
            uint32_t a2 = __float_as_uint(Ps[R * QST + ks + 4 + lc]);
            uint32_t a3 = __float_as_uint(Ps[(R + 8) * QST + ks + 4 + lc]);
            #pragma unroll
            for (int j = 0; j < 4; j++) {
                int n = swn * 32 + j * 8 + lr;
                uint32_t b0 = __float_as_uint(Vs[(ks + lc) * VST + n]);
                uint32_t b1 = __float_as_uint(Vs[(ks + lc + 4) * VST + n]);
                mma_tf32(oacc[j], a0, a1, a2, a3, b0, b1);
            }
        }
    }

    // Finalize: divide by denominator, write g_o
    {
        float inv0 = 1.0f / l_s[R];
        float inv1 = 1.0f / l_s[R + 8];
        size_t row0 = (size_t)(b * N_ + q0 + R) * DIM_;
        size_t row1 = (size_t)(b * N_ + q0 + R + 8) * DIM_;
        #pragma unroll
        for (int j = 0; j < 4; j++) {
            int col = h * D_ + swn * 32 + j * 8 + 2 * lc;
            float2 v0 = {oacc[j][0] * inv0, oacc[j][1] * inv0};
            float2 v1 = {oacc[j][2] * inv1, oacc[j][3] * inv1};
            *(float2*)(g_o + row0 + col) = v0;
            *(float2*)(g_o + row1 + col) = v1;
        }
    }
}

// ---------------------------------------------------------------------------
// Launch
// ---------------------------------------------------------------------------
extern "C" void kernel_launch(void* const* d_in, const int* in_sizes, int n_in,
                              void* d_out, int out_size) {
    const float* x   = (const float*)d_in[0];
    const float* mem = (const float*)d_in[1];
    const float* em  = (const float*)d_in[2];
    const float* Wq  = (const float*)d_in[3];
    const float* Wkv = (const float*)d_in[4];
    const float* Wo  = (const float*)d_in[5];
    const float* bo  = (const float*)d_in[6];
    float* out = (float*)d_out;

    float *ctxp, *qp, *kvp, *op;
    cudaGetSymbolAddress((void**)&ctxp, g_ctx);
    cudaGetSymbolAddress((void**)&qp,   g_q);
    cudaGetSymbolAddress((void**)&kvp,  g_kv);
    cudaGetSymbolAddress((void**)&op,   g_o);

    // 1) pack context
    {
        size_t total4 = (size_t)B_ * J_ * DIM_ / 4;
        int thr = 256;
        int blk = (int)((total4 + thr - 1) / thr);
        pack_ctx_kernel<<<blk, thr>>>(x, mem);
    }

    // 2) Q = X @ Wq          [4096,1024]
    {
        dim3 grid(DIM_ / 128, (B_ * N_) / 128);
        gemm_tf32<<<grid, 256>>>(x, Wq, qp, nullptr, B_ * N_, DIM_, DIM_);
    }

    // 3) KV = ctx @ Wkv      [8192,2048]
    {
        dim3 grid((2 * DIM_) / 128, (B_ * J_) / 128);
        gemm_tf32<<<grid, 256>>>(ctxp, Wkv, kvp, nullptr, B_ * J_, 2 * DIM_, DIM_);
    }

    // 4) flash attention (tensor cores) -> g_o
    {
        int smemBytes = (BQ * QST * 3 + BJ * VST + 3 * BQ + 256) * (int)sizeof(float);
        cudaFuncSetAttribute(attn_tc_kernel, cudaFuncAttributeMaxDynamicSharedMemorySize,
                             smemBytes);
        dim3 grid(N_ / BQ, B_ * H_);
        attn_tc_kernel<<<grid, 256, smemBytes>>>(em);
    }

    // 5) out = g_o @ Wo + bo
    {
        dim3 grid(DIM_ / 128, (B_ * N_) / 128);
        gemm_tf32<<<grid, 256>>>(op, Wo, out, bo, B_ * N_, DIM_, DIM_);
    }
}

// round 4
// speedup vs baseline: 4.3661x; 1.3253x over previous
#include <cuda_runtime.h>
#include <math.h>
#include <stdint.h>

// Problem constants
#define B_    2
#define N_    2048
#define MEM_  2048
#define DIM_  1024
#define H_    16
#define D_    64
#define J_    (MEM_ + N_)   // 4096

// Scratch (device globals: allocation-free per harness rules)
__device__ float g_ctx[B_ * J_ * DIM_];         // 32 MB  concat(mem, x)
__device__ float g_q  [B_ * N_ * DIM_];         // 16 MB  Q = X @ Wq
__device__ float g_kv [B_ * J_ * 2 * DIM_];     // 64 MB  KV = ctx @ Wkv
__device__ float g_o  [B_ * N_ * DIM_];         // 16 MB  attention output (pre-Wo)

// ---------------------------------------------------------------------------
// Helpers
// ---------------------------------------------------------------------------
__device__ __forceinline__ float cvt_tf32(float x) {
    uint32_t u;
    asm("cvt.rna.tf32.f32 %0, %1;" : "=r"(u) : "f"(x));
    return __uint_as_float(u);
}

__device__ __forceinline__ void mma_tf32(float c[4],
                                         uint32_t a0, uint32_t a1, uint32_t a2, uint32_t a3,
                                         uint32_t b0, uint32_t b1) {
    asm volatile(
        "mma.sync.aligned.m16n8k8.row.col.f32.tf32.tf32.f32 "
        "{%0,%1,%2,%3}, {%4,%5,%6,%7}, {%8,%9}, {%0,%1,%2,%3};"
        : "+f"(c[0]), "+f"(c[1]), "+f"(c[2]), "+f"(c[3])
        : "r"(a0), "r"(a1), "r"(a2), "r"(a3), "r"(b0), "r"(b1));
}

// Fast 2^x on the FMA/ALU pipes (no MUFU). Valid for x <= ~1; clamps below -80.
__device__ __forceinline__ float fexp2(float x) {
    x = fmaxf(x, -80.0f);
    float t = x + 12582912.0f;              // 1.5 * 2^23 : round-to-nearest int
    float f = x - (t - 12582912.0f);        // f in [-0.5, 0.5]
    float p = 1.3333558e-3f;
    p = fmaf(p, f, 9.6181291e-3f);
    p = fmaf(p, f, 5.5504109e-2f);
    p = fmaf(p, f, 2.4022651e-1f);
    p = fmaf(p, f, 6.9314718e-1f);
    p = fmaf(p, f, 1.0f);
    return __int_as_float(__float_as_int(p) + (__float_as_int(t) << 23));
}

// ---------------------------------------------------------------------------
// Pack context = concat(mem, x) along sequence dim
// ---------------------------------------------------------------------------
__global__ void pack_ctx_kernel(const float* __restrict__ x,
                                const float* __restrict__ mem) {
    const size_t total4 = (size_t)B_ * J_ * DIM_ / 4;
    size_t idx = (size_t)blockIdx.x * blockDim.x + threadIdx.x;
    if (idx >= total4) return;
    size_t e = idx * 4;
    int b = (int)(e / ((size_t)J_ * DIM_));
    size_t r = e % ((size_t)J_ * DIM_);
    int j = (int)(r / DIM_);
    int c = (int)(r % DIM_);
    float4 v;
    if (j < MEM_) v = *(const float4*)(mem + ((size_t)b * MEM_ + j) * DIM_ + c);
    else          v = *(const float4*)(x   + ((size_t)b * N_ + (j - MEM_)) * DIM_ + c);
    *(float4*)(g_ctx + e) = v;
}

// ---------------------------------------------------------------------------
// TF32 tensor-core GEMM: C[M,N] = A[M,K] @ B[K,N] (+bias)   (same as R2)
// ---------------------------------------------------------------------------
#define G_AST 36
#define G_BST 136

__global__ void __launch_bounds__(256)
gemm_tf32(const float* __restrict__ A, const float* __restrict__ Bm,
          float* __restrict__ C, const float* __restrict__ bias,
          int M, int Nn, int K) {
    __shared__ float As[128 * G_AST];
    __shared__ float Bs[32 * G_BST];

    const int tid = threadIdx.x;
    const int w = tid >> 5, lane = tid & 31;
    const int wm = w >> 2, wn = w & 3;
    const int lr = lane >> 2, lc = lane & 3;
    const int mBase = blockIdx.y * 128;
    const int nBase = blockIdx.x * 128;

    float acc[4][4][4] = {};

    for (int k0 = 0; k0 < K; k0 += 32) {
        #pragma unroll
        for (int i = 0; i < 4; i++) {
            int idx = tid + i * 256;
            int r = idx >> 3, c4 = (idx & 7) * 4;
            float4 v = *(const float4*)(A + (size_t)(mBase + r) * K + k0 + c4);
            float4 t;
            t.x = cvt_tf32(v.x); t.y = cvt_tf32(v.y);
            t.z = cvt_tf32(v.z); t.w = cvt_tf32(v.w);
            *(float4*)(As + r * G_AST + c4) = t;
        }
        #pragma unroll
        for (int i = 0; i < 4; i++) {
            int idx = tid + i * 256;
            int r = idx >> 5, c4 = (idx & 31) * 4;
            float4 v = *(const float4*)(Bm + (size_t)(k0 + r) * Nn + nBase + c4);
            float4 t;
            t.x = cvt_tf32(v.x); t.y = cvt_tf32(v.y);
            t.z = cvt_tf32(v.z); t.w = cvt_tf32(v.w);
            *(float4*)(Bs + r * G_BST + c4) = t;
        }
        __syncthreads();

        #pragma unroll
        for (int ks = 0; ks < 32; ks += 8) {
            uint32_t af[4][4], bf[4][2];
            #pragma unroll
            for (int i = 0; i < 4; i++) {
                int R = wm * 64 + i * 16 + lr;
                af[i][0] = __float_as_uint(As[R * G_AST + ks + lc]);
                af[i][1] = __float_as_uint(As[(R + 8) * G_AST + ks + lc]);
                af[i][2] = __float_as_uint(As[R * G_AST + ks + 4 + lc]);
                af[i][3] = __float_as_uint(As[(R + 8) * G_AST + ks + 4 + lc]);
            }
            #pragma unroll
            for (int j = 0; j < 4; j++) {
                int Cn = wn * 32 + j * 8 + lr;
                bf[j][0] = __float_as_uint(Bs[(ks + lc) * G_BST + Cn]);
                bf[j][1] = __float_as_uint(Bs[(ks + lc + 4) * G_BST + Cn]);
            }
            #pragma unroll
            for (int i = 0; i < 4; i++)
                #pragma unroll
                for (int j = 0; j < 4; j++)
                    mma_tf32(acc[i][j], af[i][0], af[i][1], af[i][2], af[i][3],
                             bf[j][0], bf[j][1]);
        }
        __syncthreads();
    }

    #pragma unroll
    for (int i = 0; i < 4; i++) {
        int r0 = mBase + wm * 64 + i * 16 + lr;
        #pragma unroll
        for (int j = 0; j < 4; j++) {
            int n0 = nBase + wn * 32 + j * 8 + 2 * lc;
            float b0v = bias ? bias[n0] : 0.0f;
            float b1v = bias ? bias[n0 + 1] : 0.0f;
            float2 v0 = {acc[i][j][0] + b0v, acc[i][j][1] + b1v};
            float2 v1 = {acc[i][j][2] + b0v, acc[i][j][3] + b1v};
            *(float2*)(C + (size_t)r0 * Nn + n0) = v0;
            *(float2*)(C + (size_t)(r0 + 8) * Nn + n0) = v1;
        }
    }
}

// ---------------------------------------------------------------------------
// Flash attention: warp-owns-rows, register softmax, FMA exp2, rna tf32 cvts.
// BQ=128 (8 warps x 16 rows), BJ=64.
// ---------------------------------------------------------------------------
#define BQ 128
#define BJ 64
#define QST 68   // Qs/Ks stride (words): bank = 4r + c  -> conflict-free frags
#define VST 72   // Vs stride (words):    bank = 8k + n  -> conflict-free frags

__global__ void __launch_bounds__(256)
attn_tc_kernel(const float* __restrict__ em) {
    extern __shared__ float smf[];
    float* Qs = smf;                    // [128][68]
    float* Ks = Qs + BQ * QST;          // [64][68]
    float* Vs = Ks + BJ * QST;          // [64][72]

    const int tid = threadIdx.x;
    const int w = tid >> 5, lane = tid & 31;
    const int lr = lane >> 2, lc = lane & 3;
    const int bh = blockIdx.y;
    const int b = bh / H_, h = bh % H_;
    const int q0 = blockIdx.x * BQ;
    const int R = w * 16 + lr;          // warp-local base row (0..127)

    const float QSCALE = 0.125f * 1.44269504f;   // d^-0.5 * log2(e)

    // Load Q tile (scaled, cvt.rna to tf32)
    #pragma unroll
    for (int i = 0; i < 8; i++) {
        int idx = tid + i * 256;
        int r = idx >> 4, c4 = (idx & 15) * 4;
        float4 v = *(const float4*)(g_q + ((size_t)(b * N_ + q0 + r)) * DIM_ + h * D_ + c4);
        float4 t;
        t.x = cvt_tf32(v.x * QSCALE); t.y = cvt_tf32(v.y * QSCALE);
        t.z = cvt_tf32(v.z * QSCALE); t.w = cvt_tf32(v.w * QSCALE);
        *(float4*)(Qs + r * QST + c4) = t;
    }

    float m0 = -1e30f, m1 = -1e30f, l0 = 0.0f, l1 = 0.0f;
    float oacc[8][4] = {};

    const int njEnd = q0 + MEM_ + BQ;
    for (int j0 = 0; j0 < njEnd; j0 += BJ) {
        // Load K, V tiles (cvt.rna to tf32)
        #pragma unroll
        for (int i = 0; i < 4; i++) {
            int idx = tid + i * 256;
            int r = idx >> 4, c4 = (idx & 15) * 4;
            const float* kvb = g_kv + ((size_t)(b * J_ + j0 + r)) * (2 * DIM_);
            float4 kv4 = *(const float4*)(kvb + h * D_ + c4);
            float4 vv4 = *(const float4*)(kvb + DIM_ + h * D_ + c4);
            float4 kt, vt;
            kt.x = cvt_tf32(kv4.x); kt.y = cvt_tf32(kv4.y);
            kt.z = cvt_tf32(kv4.z); kt.w = cvt_tf32(kv4.w);
            vt.x = cvt_tf32(vv4.x); vt.y = cvt_tf32(vv4.y);
            vt.z = cvt_tf32(vv4.z); vt.w = cvt_tf32(vv4.w);
            *(float4*)(Ks + r * QST + c4) = kt;
            *(float4*)(Vs + r * VST + c4) = vt;
        }
        __syncthreads();

        // ---- S = Q @ K^T (warp tile 16 x 64) ----
        float sc[8][4] = {};
        #pragma unroll
        for (int ks = 0; ks < D_; ks += 8) {
            uint32_t a0 = __float_as_uint(Qs[R * QST + ks + lc]);
            uint32_t a1 = __float_as_uint(Qs[(R + 8) * QST + ks + lc]);
            uint32_t a2 = __float_as_uint(Qs[R * QST + ks + 4 + lc]);
            uint32_t a3 = __float_as_uint(Qs[(R + 8) * QST + ks + 4 + lc]);
            #pragma unroll
            for (int j = 0; j < 8; j++) {
                int n = j * 8 + lr;
                uint32_t b0 = __float_as_uint(Ks[n * QST + ks + lc]);
                uint32_t b1 = __float_as_uint(Ks[n * QST + ks + 4 + lc]);
                mma_tf32(sc[j], a0, a1, a2, a3, b0, b1);
            }
        }

        // ---- Causal mask (only near-diagonal tiles) ----
        if (j0 + BJ - 1 > q0 + MEM_) {
            int lim0 = q0 + R + MEM_ - j0;       // row R allows local col <= lim0
            #pragma unroll
            for (int j = 0; j < 8; j++) {
                int c = j * 8 + 2 * lc;
                if (c     > lim0)     sc[j][0] = -1e30f;
                if (c + 1 > lim0)     sc[j][1] = -1e30f;
                if (c     > lim0 + 8) sc[j][2] = -1e30f;
                if (c + 1 > lim0 + 8) sc[j][3] = -1e30f;
            }
        }

        // ---- Register softmax (base 2), expire gate in numerator ----
        float t0 = -1e30f, t1 = -1e30f;
        #pragma unroll
        for (int j = 0; j < 8; j++) {
            t0 = fmaxf(t0, fmaxf(sc[j][0], sc[j][1]));
            t1 = fmaxf(t1, fmaxf(sc[j][2], sc[j][3]));
        }
        t0 = fmaxf(t0, __shfl_xor_sync(0xffffffffu, t0, 1));
        t0 = fmaxf(t0, __shfl_xor_sync(0xffffffffu, t0, 2));
        t1 = fmaxf(t1, __shfl_xor_sync(0xffffffffu, t1, 1));
        t1 = fmaxf(t1, __shfl_xor_sync(0xffffffffu, t1, 2));
        float m0n = fmaxf(m0, t0), m1n = fmaxf(m1, t1);
        float al0 = fexp2(m0 - m0n), al1 = fexp2(m1 - m1n);
        m0 = m0n; m1 = m1n;

        float s0 = 0.0f, s1 = 0.0f;
        const float* emp = em + (size_t)b * J_ + j0 + 2 * lc;
        #pragma unroll
        for (int j = 0; j < 8; j++) {
            float e00 = fexp2(sc[j][0] - m0);
            float e01 = fexp2(sc[j][1] - m0);
            float e10 = fexp2(sc[j][2] - m1);
            float e11 = fexp2(sc[j][3] - m1);
            s0 += e00 + e01;
            s1 += e10 + e11;
            float2 emv = __ldg((const float2*)(emp + j * 8));
            sc[j][0] = cvt_tf32(e00 * emv.x); sc[j][1] = cvt_tf32(e01 * emv.y);
            sc[j][2] = cvt_tf32(e10 * emv.x); sc[j][3] = cvt_tf32(e11 * emv.y);
        }
        s0 += __shfl_xor_sync(0xffffffffu, s0, 1);
        s0 += __shfl_xor_sync(0xffffffffu, s0, 2);
        s1 += __shfl_xor_sync(0xffffffffu, s1, 1);
        s1 += __shfl_xor_sync(0xffffffffu, s1, 2);
        l0 = l0 * al0 + s0;
        l1 = l1 * al1 + s1;

        #pragma unroll
        for (int j = 0; j < 8; j++) {
            oacc[j][0] *= al0; oacc[j][1] *= al0;
            oacc[j][2] *= al1; oacc[j][3] *= al1;
        }

        // ---- O += P @ V : C-frag -> A-frag via shuffles, then mma ----
        const int src0 = (lane & ~3) | (lc >> 1);
        const int src2 = src0 + 2;
        const bool odd = (lc & 1);
        #pragma unroll
        for (int g = 0; g < 8; g++) {
            float v00 = __shfl_sync(0xffffffffu, sc[g][0], src0);
            float v01 = __shfl_sync(0xffffffffu, sc[g][1], src0);
            float v20 = __shfl_sync(0xffffffffu, sc[g][0], src2);
            float v21 = __shfl_sync(0xffffffffu, sc[g][1], src2);
            float v10 = __shfl_sync(0xffffffffu, sc[g][2], src0);
            float v11 = __shfl_sync(0xffffffffu, sc[g][3], src0);
            float v30 = __shfl_sync(0xffffffffu, sc[g][2], src2);
            float v31 = __shfl_sync(0xffffffffu, sc[g][3], src2);
            uint32_t a0 = __float_as_uint(odd ? v01 : v00);
            uint32_t a1 = __float_as_uint(odd ? v11 : v10);
            uint32_t a2 = __float_as_uint(odd ? v21 : v20);
            uint32_t a3 = __float_as_uint(odd ? v31 : v30);
            #pragma unroll
            for (int j = 0; j < 8; j++) {
                int n = j * 8 + lr;
                uint32_t b0 = __float_as_uint(Vs[(g * 8 + lc) * VST + n]);
                uint32_t b1 = __float_as_uint(Vs[(g * 8 + lc + 4) * VST + n]);
                mma_tf32(oacc[j], a0, a1, a2, a3, b0, b1);
            }
        }
        __syncthreads();   // before next tile's loads overwrite Ks/Vs
    }

    // ---- Finalize ----
    {
        float inv0 = 1.0f / l0;
        float inv1 = 1.0f / l1;
        size_t row0 = (size_t)(b * N_ + q0 + R) * DIM_;
        size_t row1 = (size_t)(b * N_ + q0 + R + 8) * DIM_;
        #pragma unroll
        for (int j = 0; j < 8; j++) {
            int col = h * D_ + j * 8 + 2 * lc;
            float2 v0 = {oacc[j][0] * inv0, oacc[j][1] * inv0};
            float2 v1 = {oacc[j][2] * inv1, oacc[j][3] * inv1};
            *(float2*)(g_o + row0 + col) = v0;
            *(float2*)(g_o + row1 + col) = v1;
        }
    }
}

// ---------------------------------------------------------------------------
// Launch
// ---------------------------------------------------------------------------
extern "C" void kernel_launch(void* const* d_in, const int* in_sizes, int n_in,
                              void* d_out, int out_size) {
    const float* x   = (const float*)d_in[0];
    const float* mem = (const float*)d_in[1];
    const float* em  = (const float*)d_in[2];
    const float* Wq  = (const float*)d_in[3];
    const float* Wkv = (const float*)d_in[4];
    const float* Wo  = (const float*)d_in[5];
    const float* bo  = (const float*)d_in[6];
    float* out = (float*)d_out;

    float *ctxp, *qp, *kvp, *op;
    cudaGetSymbolAddress((void**)&ctxp, g_ctx);
    cudaGetSymbolAddress((void**)&qp,   g_q);
    cudaGetSymbolAddress((void**)&kvp,  g_kv);
    cudaGetSymbolAddress((void**)&op,   g_o);

    // 1) pack context
    {
        size_t total4 = (size_t)B_ * J_ * DIM_ / 4;
        int thr = 256;
        int blk = (int)((total4 + thr - 1) / thr);
        pack_ctx_kernel<<<blk, thr>>>(x, mem);
    }

    // 2) Q = X @ Wq
    {
        dim3 grid(DIM_ / 128, (B_ * N_) / 128);
        gemm_tf32<<<grid, 256>>>(x, Wq, qp, nullptr, B_ * N_, DIM_, DIM_);
    }

    // 3) KV = ctx @ Wkv
    {
        dim3 grid((2 * DIM_) / 128, (B_ * J_) / 128);
        gemm_tf32<<<grid, 256>>>(ctxp, Wkv, kvp, nullptr, B_ * J_, 2 * DIM_, DIM_);
    }

    // 4) flash attention (register softmax, FMA exp2) -> g_o
    {
        int smemBytes = (BQ * QST + BJ * QST + BJ * VST) * (int)sizeof(float); // ~69 KB
        cudaFuncSetAttribute(attn_tc_kernel, cudaFuncAttributeMaxDynamicSharedMemorySize,
                             smemBytes);
        dim3 grid(N_ / BQ, B_ * H_);
        attn_tc_kernel<<<grid, 256, smemBytes>>>(em);
    }

    // 5) out = g_o @ Wo + bo
    {
        dim3 grid(DIM_ / 128, (B_ * N_) / 128);
        gemm_tf32<<<grid, 256>>>(op, Wo, out, bo, B_ * N_, DIM_, DIM_);
    }
}